// round 3
// baseline (speedup 1.0000x reference)
#include <cuda_runtime.h>
#include <math.h>

#define N_NODES 100000
#define N_EDGES 1600000
#define DIMF    128
#define OUTD_F  40
#define SCAN_B  1024
#define NB_SCAN 98   // ceil(100000/1024)

// ---------------- scratch (device globals; no allocation allowed) ----------
__device__ int   g_is64;                 // 1 if edge_index stored as int64
__device__ int   g_deg[N_NODES];
__device__ float g_invdeg[N_NODES];
__device__ int   g_off[N_NODES + 1];
__device__ int   g_cursor[N_NODES];
__device__ int   g_bsums[NB_SCAN];
__device__ int   g_csc[N_EDGES];
__device__ __align__(16) float g_agg[(size_t)N_NODES * DIMF];
__device__ __align__(16) float g_h0 [(size_t)N_NODES * DIMF];
__device__ __align__(16) float g_h1 [(size_t)N_NODES * DIMF];

__device__ __forceinline__ const float* sel_src(int sel, const float* xin) {
    return sel == 0 ? xin : (sel == 1 ? g_h0 : g_h1);
}
__device__ __forceinline__ float* sel_dst(int sel, float* outp) {
    return sel == 0 ? g_h0 : (sel == 1 ? g_h1 : outp);
}

// fetch edge endpoint i from the edge buffer under either dtype
__device__ __forceinline__ int edge_at(const int* __restrict__ e32, int i) {
    // int64 layout: value i lives at word 2*i (little-endian, values < 2^31)
    return g_is64 ? e32[2 * i] : e32[i];
}

// ---------------- dtype detection ------------------------------------------
// If int64: odd words of the buffer are all zero. Sample first 2048 words.
__global__ void k_detect(const int* __restrict__ e32) {
    __shared__ int nonzero;
    if (threadIdx.x == 0) nonzero = 0;
    __syncthreads();
    for (int i = threadIdx.x; i < 1024; i += blockDim.x)
        if (e32[2 * i + 1] != 0) nonzero = 1;   // benign race: any writer sets 1
    __syncthreads();
    if (threadIdx.x == 0) g_is64 = (nonzero == 0);
}

// ---------------- graph preprocessing --------------------------------------
__global__ void k_zero_deg() {
    int i = blockIdx.x * blockDim.x + threadIdx.x;
    if (i < N_NODES) g_deg[i] = 0;
}

__global__ void k_hist(const int* __restrict__ e32) {
    int e = blockIdx.x * blockDim.x + threadIdx.x;
    if (e < N_EDGES) {
        int d = edge_at(e32, N_EDGES + e);
        if ((unsigned)d < N_NODES) atomicAdd(&g_deg[d], 1);
    }
}

__global__ void k_scan1() {
    __shared__ int sh[SCAN_B];
    int t = threadIdx.x;
    int i = blockIdx.x * SCAN_B + t;
    int v = (i < N_NODES) ? g_deg[i] : 0;
    sh[t] = v;
    __syncthreads();
    for (int s = 1; s < SCAN_B; s <<= 1) {
        int prev = (t >= s) ? sh[t - s] : 0;
        __syncthreads();
        sh[t] += prev;
        __syncthreads();
    }
    if (i < N_NODES) g_off[i] = sh[t] - v;     // exclusive within block
    if (t == SCAN_B - 1) g_bsums[blockIdx.x] = sh[t];
}

__global__ void k_scan2() {
    int run = 0;
    for (int b = 0; b < NB_SCAN; b++) {
        int t = g_bsums[b];
        g_bsums[b] = run;
        run += t;
    }
}

__global__ void k_scan3() {
    int i = blockIdx.x * blockDim.x + threadIdx.x;
    if (i < N_NODES) {
        int o = g_off[i] + g_bsums[i >> 10];
        g_off[i] = o;
        g_cursor[i] = o;
        int d = g_deg[i];
        g_invdeg[i] = 1.0f / (float)(d > 1 ? d : 1);
    }
    if (i == 0) g_off[N_NODES] = N_EDGES;
}

__global__ void k_fill_csc(const int* __restrict__ e32) {
    int e = blockIdx.x * blockDim.x + threadIdx.x;
    if (e < N_EDGES) {
        int s = edge_at(e32, e);
        int d = edge_at(e32, N_EDGES + e);
        if ((unsigned)s < N_NODES && (unsigned)d < N_NODES) {
            int p = atomicAdd(&g_cursor[d], 1);
            g_csc[p] = s;
        }
    }
}

// ---------------- mean aggregation (gather, no float atomics) --------------
// one warp per (node, 32-float chunk); 4 chunks per node. writes g_agg.
__global__ void k_agg(const float* __restrict__ xin, int sel) {
    int warp = (blockIdx.x * blockDim.x + threadIdx.x) >> 5;
    int lane = threadIdx.x & 31;
    if (warp >= N_NODES * 4) return;
    const float* H = sel_src(sel, xin);
    int n = warp >> 2;
    int c = warp & 3;
    int base = c * 32 + lane;
    const float* Hp = H + base;
    int j = g_off[n], je = g_off[n + 1];
    float acc = 0.f;
    for (; j + 3 < je; j += 4) {
        int s0 = g_csc[j], s1 = g_csc[j + 1], s2 = g_csc[j + 2], s3 = g_csc[j + 3];
        float v0 = Hp[(size_t)s0 * DIMF];
        float v1 = Hp[(size_t)s1 * DIMF];
        float v2 = Hp[(size_t)s2 * DIMF];
        float v3 = Hp[(size_t)s3 * DIMF];
        acc += v0; acc += v1; acc += v2; acc += v3;
    }
    for (; j < je; j++) acc += Hp[(size_t)g_csc[j] * DIMF];
    g_agg[(size_t)n * DIMF + base] = acc * g_invdeg[n];
}

// ---------------- fused dual GEMM:  C = g_agg@Wl^T + X@Wr^T + b -----------
// K = 256 (first 128 from g_agg/Wl, next 128 from X/Wr). Tile: 64 rows.
template <int OUTD>
__global__ void k_gemm(const float* __restrict__ xin, int selIn,
                       const float* __restrict__ Wl, const float* __restrict__ Wr,
                       const float* __restrict__ bias,
                       float* __restrict__ outp, int selOut) {
    __shared__ float As[64][36];          // 64x32 tile, stride 36 (9*16B rows)
    __shared__ float Ws[32][OUTD + 1];    // [k][c], pad -> conflict-free

    const float* X = sel_src(selIn, xin);
    float* C = sel_dst(selOut, outp);

    int tid = threadIdx.x;
    int tc = tid & 15;        // 16 column groups
    int tr = tid >> 4;        // 16 row groups
    int row0 = blockIdx.x * 64;

    float acc[4][8];
#pragma unroll
    for (int i = 0; i < 4; i++)
#pragma unroll
        for (int j = 0; j < 8; j++) acc[i][j] = 0.f;

#pragma unroll 1
    for (int kt = 0; kt < 8; kt++) {
        int k0 = kt * 32;
        const float* Asrc = (k0 < 128) ? g_agg : X;
        const float* Wsrc = (k0 < 128) ? Wl : Wr;
        int ka = k0 & 127;

        // A tile: 2048 floats = 512 float4, 2 per thread
#pragma unroll
        for (int i = 0; i < 2; i++) {
            int lin = tid + i * 256;          // float4 index
            int r = lin >> 3, kk4 = lin & 7;
            int gr = row0 + r;
            float4 v = make_float4(0.f, 0.f, 0.f, 0.f);
            if (gr < N_NODES)
                v = *(const float4*)(Asrc + (size_t)gr * DIMF + ka + kk4 * 4);
            *(float4*)&As[r][kk4 * 4] = v;
        }
        // W tile: Ws[kk][c] = Wsrc[c*128 + ka + kk]
        {
            int lane = tid & 31, cb = tid >> 5;
#pragma unroll
            for (int c = cb; c < OUTD; c += 8)
                Ws[lane][c] = Wsrc[c * DIMF + ka + lane];
        }
        __syncthreads();

#pragma unroll
        for (int kk = 0; kk < 32; kk++) {
            float a[4], bb[8];
#pragma unroll
            for (int i = 0; i < 4; i++) a[i] = As[tr * 4 + i][kk];
#pragma unroll
            for (int j = 0; j < 8; j++) {
                int c = tc + 16 * j;
                bb[j] = (c < OUTD) ? Ws[kk][c] : 0.f;
            }
#pragma unroll
            for (int i = 0; i < 4; i++)
#pragma unroll
                for (int j = 0; j < 8; j++) acc[i][j] = fmaf(a[i], bb[j], acc[i][j]);
        }
        __syncthreads();
    }

#pragma unroll
    for (int i = 0; i < 4; i++) {
        int gr = row0 + tr * 4 + i;
        if (gr >= N_NODES) continue;
#pragma unroll
        for (int j = 0; j < 8; j++) {
            int c = tc + 16 * j;
            if (c < OUTD) C[(size_t)gr * OUTD + c] = acc[i][j] + bias[c];
        }
    }
}

// ---------------- L2-normalize + ReLU (warp per row, 128 dims) -------------
__global__ void k_norm_relu(int sel) {
    int warp = (blockIdx.x * blockDim.x + threadIdx.x) >> 5;
    int lane = threadIdx.x & 31;
    if (warp >= N_NODES) return;
    float* H = sel == 0 ? g_h0 : g_h1;
    float4* p = (float4*)(H + (size_t)warp * DIMF + lane * 4);
    float4 v = *p;
    float ss = v.x * v.x + v.y * v.y + v.z * v.z + v.w * v.w;
#pragma unroll
    for (int s = 16; s; s >>= 1) ss += __shfl_xor_sync(0xFFFFFFFFu, ss, s);
    float nrm = sqrtf(ss);
    float sc = 1.0f / fmaxf(nrm, 1e-12f);
    v.x = fmaxf(v.x * sc, 0.f);
    v.y = fmaxf(v.y * sc, 0.f);
    v.z = fmaxf(v.z * sc, 0.f);
    v.w = fmaxf(v.w * sc, 0.f);
    *p = v;
}

// ---------------- softmax over 40 cols (warp per row, in place) ------------
__global__ void k_softmax(float* __restrict__ C) {
    int warp = (blockIdx.x * blockDim.x + threadIdx.x) >> 5;
    int lane = threadIdx.x & 31;
    if (warp >= N_NODES) return;
    float* row = C + (size_t)warp * OUTD_F;
    float a0 = row[lane];                                   // lane < 32 < 40
    float a1 = (lane + 32 < OUTD_F) ? row[lane + 32] : -1e30f;
    float m = fmaxf(a0, a1);
#pragma unroll
    for (int s = 16; s; s >>= 1) m = fmaxf(m, __shfl_xor_sync(0xFFFFFFFFu, m, s));
    float e0 = __expf(a0 - m);
    float e1 = (lane + 32 < OUTD_F) ? __expf(a1 - m) : 0.f;
    float sum = e0 + e1;
#pragma unroll
    for (int s = 16; s; s >>= 1) sum += __shfl_xor_sync(0xFFFFFFFFu, sum, s);
    float inv = 1.0f / sum;
    row[lane] = e0 * inv;
    if (lane + 32 < OUTD_F) row[lane + 32] = e1 * inv;
}

// ---------------- launch ----------------------------------------------------
extern "C" void kernel_launch(void* const* d_in, const int* in_sizes, int n_in,
                              void* d_out, int out_size) {
    const float* x   = (const float*)d_in[0];
    const int*   e32 = (const int*)d_in[1];     // edge_index words (int32 or int64)
    const float* Wl0 = (const float*)d_in[2];
    const float* Wr0 = (const float*)d_in[3];
    const float* b0  = (const float*)d_in[4];
    const float* Wl1 = (const float*)d_in[5];
    const float* Wr1 = (const float*)d_in[6];
    const float* b1  = (const float*)d_in[7];
    const float* Wl2 = (const float*)d_in[8];
    const float* Wr2 = (const float*)d_in[9];
    const float* b2  = (const float*)d_in[10];
    float* out = (float*)d_out;

    const int TB = 256;
    int nblk_nodes = (N_NODES + TB - 1) / TB;           // 391
    int nblk_edges = (N_EDGES + TB - 1) / TB;           // 6250
    int nblk_agg   = (N_NODES * 4 * 32 + TB - 1) / TB;  // 50000
    int nblk_gemm  = (N_NODES + 63) / 64;               // 1563
    int nblk_rows  = (N_NODES * 32 + TB - 1) / TB;      // 12500

    // ---- dtype detect + build CSC ----
    k_detect<<<1, TB>>>(e32);
    k_zero_deg<<<nblk_nodes, TB>>>();
    k_hist<<<nblk_edges, TB>>>(e32);
    k_scan1<<<NB_SCAN, SCAN_B>>>();
    k_scan2<<<1, 1>>>();
    k_scan3<<<nblk_nodes, TB>>>();
    k_fill_csc<<<nblk_edges, TB>>>(e32);

    // ---- layer 0: agg(x) ; h0 = gemm(agg, x) ; norm_relu(h0) ----
    k_agg<<<nblk_agg, TB>>>(x, 0);
    k_gemm<128><<<nblk_gemm, TB>>>(x, 0, Wl0, Wr0, b0, nullptr, 0);
    k_norm_relu<<<nblk_rows, TB>>>(0);

    // ---- layer 1: agg(h0) ; h1 = gemm(agg, h0) ; norm_relu(h1) ----
    k_agg<<<nblk_agg, TB>>>(nullptr, 1);
    k_gemm<128><<<nblk_gemm, TB>>>(nullptr, 1, Wl1, Wr1, b1, nullptr, 1);
    k_norm_relu<<<nblk_rows, TB>>>(1);

    // ---- layer 2: agg(h1) ; out = gemm(agg, h1) ; softmax(out) ----
    k_agg<<<nblk_agg, TB>>>(nullptr, 2);
    k_gemm<40><<<nblk_gemm, TB>>>(nullptr, 2, Wl2, Wr2, b2, out, 2);
    k_softmax<<<nblk_rows, TB>>>(out);
}

// round 4
// speedup vs baseline: 1.2782x; 1.2782x over previous
#include <cuda_runtime.h>
#include <cuda_bf16.h>
#include <math.h>

#define N_NODES 100000
#define N_EDGES 1600000
#define DIMF    128
#define OUTD_F  40
#define SCAN_B  1024
#define NB_SCAN 98   // ceil(100000/1024)

// ---------------- scratch (device globals; no allocation allowed) ----------
__device__ int   g_is64;                 // 1 if edge_index stored as int64
__device__ int   g_deg[N_NODES];
__device__ float g_invdeg[N_NODES];
__device__ int   g_off[N_NODES + 1];
__device__ int   g_cursor[N_NODES];
__device__ int   g_bsums[NB_SCAN];
__device__ int   g_csc[N_EDGES];
__device__ __align__(16) float g_h0 [(size_t)N_NODES * DIMF];
__device__ __align__(16) float g_h1 [(size_t)N_NODES * DIMF];
// bf16 split operands for tensor-core GEMM
__device__ __align__(16) __nv_bfloat16 g_agghi[(size_t)N_NODES * DIMF];
__device__ __align__(16) __nv_bfloat16 g_agglo[(size_t)N_NODES * DIMF];
__device__ __align__(16) __nv_bfloat16 g_xhi  [(size_t)N_NODES * DIMF];
__device__ __align__(16) __nv_bfloat16 g_xlo  [(size_t)N_NODES * DIMF];
__device__ __align__(16) __nv_bfloat16 g_Wlhi[DIMF * DIMF], g_Wllo[DIMF * DIMF];
__device__ __align__(16) __nv_bfloat16 g_Wrhi[DIMF * DIMF], g_Wrlo[DIMF * DIMF];

__device__ __forceinline__ const float* sel_src(int sel, const float* xin) {
    return sel == 0 ? xin : (sel == 1 ? g_h0 : g_h1);
}
__device__ __forceinline__ float* sel_dst(int sel, float* outp) {
    return sel == 0 ? g_h0 : (sel == 1 ? g_h1 : outp);
}

__device__ __forceinline__ int edge_at(const int* __restrict__ e32, int i) {
    return g_is64 ? e32[2 * i] : e32[i];
}

__device__ __forceinline__ void split2(float v, __nv_bfloat16& hi, __nv_bfloat16& lo) {
    hi = __float2bfloat16(v);
    lo = __float2bfloat16(v - __bfloat162float(hi));
}

// ---------------- dtype detection ------------------------------------------
__global__ void k_detect(const int* __restrict__ e32) {
    __shared__ int nonzero;
    if (threadIdx.x == 0) nonzero = 0;
    __syncthreads();
    for (int i = threadIdx.x; i < 1024; i += blockDim.x)
        if (e32[2 * i + 1] != 0) nonzero = 1;
    __syncthreads();
    if (threadIdx.x == 0) g_is64 = (nonzero == 0);
}

// ---------------- graph preprocessing --------------------------------------
__global__ void k_zero_deg() {
    int i = blockIdx.x * blockDim.x + threadIdx.x;
    if (i < N_NODES) g_deg[i] = 0;
}

__global__ void k_hist(const int* __restrict__ e32) {
    int e = blockIdx.x * blockDim.x + threadIdx.x;
    if (e < N_EDGES) {
        int d = edge_at(e32, N_EDGES + e);
        if ((unsigned)d < N_NODES) atomicAdd(&g_deg[d], 1);
    }
}

__global__ void k_scan1() {
    __shared__ int sh[SCAN_B];
    int t = threadIdx.x;
    int i = blockIdx.x * SCAN_B + t;
    int v = (i < N_NODES) ? g_deg[i] : 0;
    sh[t] = v;
    __syncthreads();
    for (int s = 1; s < SCAN_B; s <<= 1) {
        int prev = (t >= s) ? sh[t - s] : 0;
        __syncthreads();
        sh[t] += prev;
        __syncthreads();
    }
    if (i < N_NODES) g_off[i] = sh[t] - v;
    if (t == SCAN_B - 1) g_bsums[blockIdx.x] = sh[t];
}

__global__ void k_scan2() {
    int run = 0;
    for (int b = 0; b < NB_SCAN; b++) {
        int t = g_bsums[b];
        g_bsums[b] = run;
        run += t;
    }
}

__global__ void k_scan3() {
    int i = blockIdx.x * blockDim.x + threadIdx.x;
    if (i < N_NODES) {
        int o = g_off[i] + g_bsums[i >> 10];
        g_off[i] = o;
        g_cursor[i] = o;
        int d = g_deg[i];
        g_invdeg[i] = 1.0f / (float)(d > 1 ? d : 1);
    }
    if (i == 0) g_off[N_NODES] = N_EDGES;
}

__global__ void k_fill_csc(const int* __restrict__ e32) {
    int e = blockIdx.x * blockDim.x + threadIdx.x;
    if (e < N_EDGES) {
        int s = edge_at(e32, e);
        int d = edge_at(e32, N_EDGES + e);
        if ((unsigned)s < N_NODES && (unsigned)d < N_NODES) {
            int p = atomicAdd(&g_cursor[d], 1);
            g_csc[p] = s;
        }
    }
}

// ---------------- operand splitting -----------------------------------------
__global__ void k_split_x(const float* __restrict__ x) {
    for (size_t i = (size_t)blockIdx.x * blockDim.x + threadIdx.x;
         i < (size_t)N_NODES * DIMF; i += (size_t)gridDim.x * blockDim.x) {
        __nv_bfloat16 hi, lo; split2(x[i], hi, lo);
        g_xhi[i] = hi; g_xlo[i] = lo;
    }
}

__global__ void k_split_w(const float* __restrict__ Wl, const float* __restrict__ Wr, int n) {
    int i = blockIdx.x * blockDim.x + threadIdx.x;
    if (i < n) {
        __nv_bfloat16 hi, lo;
        split2(Wl[i], hi, lo); g_Wlhi[i] = hi; g_Wllo[i] = lo;
        split2(Wr[i], hi, lo); g_Wrhi[i] = hi; g_Wrlo[i] = lo;
    }
}

// ---------------- mean aggregation (gather) -> bf16 split -------------------
__global__ void k_agg(const float* __restrict__ xin, int sel) {
    int warp = (blockIdx.x * blockDim.x + threadIdx.x) >> 5;
    int lane = threadIdx.x & 31;
    if (warp >= N_NODES * 4) return;
    const float* H = sel_src(sel, xin);
    int n = warp >> 2;
    int c = warp & 3;
    int base = c * 32 + lane;
    const float* Hp = H + base;
    int j = g_off[n], je = g_off[n + 1];
    float acc = 0.f;
    for (; j + 3 < je; j += 4) {
        int s0 = g_csc[j], s1 = g_csc[j + 1], s2 = g_csc[j + 2], s3 = g_csc[j + 3];
        float v0 = Hp[(size_t)s0 * DIMF];
        float v1 = Hp[(size_t)s1 * DIMF];
        float v2 = Hp[(size_t)s2 * DIMF];
        float v3 = Hp[(size_t)s3 * DIMF];
        acc += v0; acc += v1; acc += v2; acc += v3;
    }
    for (; j < je; j++) acc += Hp[(size_t)g_csc[j] * DIMF];
    float r = acc * g_invdeg[n];
    __nv_bfloat16 hi, lo; split2(r, hi, lo);
    size_t idx = (size_t)n * DIMF + base;
    g_agghi[idx] = hi; g_agglo[idx] = lo;
}

// ---------------- tensor-core GEMM: C = agg@Wl^T + X@Wr^T + b --------------
// bf16x3: (hi+lo) operands, 3 MMA passes (hh, hl, lh), fp32 accumulate.
__device__ __forceinline__ void mma_bf16(float* d, const unsigned* a, unsigned b0, unsigned b1) {
    asm volatile(
        "mma.sync.aligned.m16n8k16.row.col.f32.bf16.bf16.f32 "
        "{%0,%1,%2,%3}, {%4,%5,%6,%7}, {%8,%9}, {%0,%1,%2,%3};\n"
        : "+f"(d[0]), "+f"(d[1]), "+f"(d[2]), "+f"(d[3])
        : "r"(a[0]), "r"(a[1]), "r"(a[2]), "r"(a[3]), "r"(b0), "r"(b1));
}

template <int OUTD>
__global__ void __launch_bounds__(256) k_gemm_mma(const float* __restrict__ bias,
                                                  float* __restrict__ outp, int selOut) {
    constexpr int MT  = (OUTD == 128) ? 2 : 1;   // m16 tiles per warp
    constexpr int NT  = (OUTD == 128) ? 8 : 5;   // n8 tiles per warp
    constexpr int STR = 20;                      // smem row stride (32-bit words)

    __shared__ __align__(16) unsigned sAh[128 * STR], sAl[128 * STR];
    __shared__ __align__(16) unsigned sWh[OUTD * STR], sWl[OUTD * STR];

    float* C = sel_dst(selOut, outp);
    int tid  = threadIdx.x;
    int wid  = tid >> 5, lane = tid & 31;
    int mw   = (OUTD == 128) ? (wid & 3) : wid;  // warp row group
    int nw   = (OUTD == 128) ? (wid >> 2) : 0;   // warp col group
    int row0 = blockIdx.x * 128;
    int lg   = lane >> 2;        // group id 0..7
    int lt   = lane & 3;         // thread in group

    float acc[MT][NT][4];
#pragma unroll
    for (int m = 0; m < MT; m++)
#pragma unroll
        for (int n = 0; n < NT; n++)
#pragma unroll
            for (int q = 0; q < 4; q++) acc[m][n][q] = 0.f;

#pragma unroll 1
    for (int kt = 0; kt < 8; kt++) {
        const unsigned* Ah = (const unsigned*)((kt < 4) ? g_agghi : g_xhi);
        const unsigned* Al = (const unsigned*)((kt < 4) ? g_agglo : g_xlo);
        const unsigned* Wh = (const unsigned*)((kt < 4) ? g_Wlhi : g_Wrhi);
        const unsigned* Wo = (const unsigned*)((kt < 4) ? g_Wllo : g_Wrlo);
        int kw = (kt & 3) * 16;   // word offset within 64-word feature row

        // A tile: 128 rows x 16 words (x2 arrays)
#pragma unroll
        for (int i = tid; i < 128 * 4; i += 256) {
            int r = i >> 2, q = (i & 3) * 4;
            uint4 vh = make_uint4(0, 0, 0, 0), vl = vh;
            if (row0 + r < N_NODES) {
                vh = *(const uint4*)(Ah + (size_t)(row0 + r) * 64 + kw + q);
                vl = *(const uint4*)(Al + (size_t)(row0 + r) * 64 + kw + q);
            }
            *(uint4*)(sAh + r * STR + q) = vh;
            *(uint4*)(sAl + r * STR + q) = vl;
        }
        // W tile: OUTD rows x 16 words (x2 arrays)
        for (int i = tid; i < OUTD * 4; i += 256) {
            int r = i >> 2, q = (i & 3) * 4;
            *(uint4*)(sWh + r * STR + q) = *(const uint4*)(Wh + (size_t)r * 64 + kw + q);
            *(uint4*)(sWl + r * STR + q) = *(const uint4*)(Wo + (size_t)r * 64 + kw + q);
        }
        __syncthreads();

#pragma unroll
        for (int ks = 0; ks < 2; ks++) {
            int wb = ks * 8;
            unsigned ah[MT][4], al[MT][4];
#pragma unroll
            for (int m = 0; m < MT; m++) {
                int rr = (mw * MT + m) * 16 + lg;
                ah[m][0] = sAh[rr * STR + wb + lt];
                ah[m][1] = sAh[(rr + 8) * STR + wb + lt];
                ah[m][2] = sAh[rr * STR + wb + 4 + lt];
                ah[m][3] = sAh[(rr + 8) * STR + wb + 4 + lt];
                al[m][0] = sAl[rr * STR + wb + lt];
                al[m][1] = sAl[(rr + 8) * STR + wb + lt];
                al[m][2] = sAl[rr * STR + wb + 4 + lt];
                al[m][3] = sAl[(rr + 8) * STR + wb + 4 + lt];
            }
#pragma unroll
            for (int n = 0; n < NT; n++) {
                int nr = nw * NT * 8 + n * 8 + lg;
                unsigned bh0 = sWh[nr * STR + wb + lt];
                unsigned bh1 = sWh[nr * STR + wb + 4 + lt];
                unsigned bl0 = sWl[nr * STR + wb + lt];
                unsigned bl1 = sWl[nr * STR + wb + 4 + lt];
#pragma unroll
                for (int m = 0; m < MT; m++) {
                    mma_bf16(acc[m][n], ah[m], bh0, bh1);   // hi*hi
                    mma_bf16(acc[m][n], ah[m], bl0, bl1);   // hi*lo
                    mma_bf16(acc[m][n], al[m], bh0, bh1);   // lo*hi
                }
            }
        }
        __syncthreads();
    }

    // epilogue: add bias, store fp32
#pragma unroll
    for (int m = 0; m < MT; m++) {
        int r = row0 + (mw * MT + m) * 16 + lg;
#pragma unroll
        for (int n = 0; n < NT; n++) {
            int c = nw * NT * 8 + n * 8 + lt * 2;
            float bv0 = bias[c], bv1 = bias[c + 1];
            if (r < N_NODES) {
                C[(size_t)r * OUTD + c]     = acc[m][n][0] + bv0;
                C[(size_t)r * OUTD + c + 1] = acc[m][n][1] + bv1;
            }
            if (r + 8 < N_NODES) {
                C[(size_t)(r + 8) * OUTD + c]     = acc[m][n][2] + bv0;
                C[(size_t)(r + 8) * OUTD + c + 1] = acc[m][n][3] + bv1;
            }
        }
    }
}

// ---------------- L2-normalize + ReLU + bf16 split (warp per row) ----------
__global__ void k_norm_relu_split(int sel) {
    int warp = (blockIdx.x * blockDim.x + threadIdx.x) >> 5;
    int lane = threadIdx.x & 31;
    if (warp >= N_NODES) return;
    float* H = sel == 0 ? g_h0 : g_h1;
    float4* p = (float4*)(H + (size_t)warp * DIMF + lane * 4);
    float4 v = *p;
    float ss = v.x * v.x + v.y * v.y + v.z * v.z + v.w * v.w;
#pragma unroll
    for (int s = 16; s; s >>= 1) ss += __shfl_xor_sync(0xFFFFFFFFu, ss, s);
    float sc = 1.0f / fmaxf(sqrtf(ss), 1e-12f);
    v.x = fmaxf(v.x * sc, 0.f);
    v.y = fmaxf(v.y * sc, 0.f);
    v.z = fmaxf(v.z * sc, 0.f);
    v.w = fmaxf(v.w * sc, 0.f);
    *p = v;
    size_t idx = (size_t)warp * DIMF + lane * 4;
    __nv_bfloat16 hi, lo;
    split2(v.x, hi, lo); g_xhi[idx]     = hi; g_xlo[idx]     = lo;
    split2(v.y, hi, lo); g_xhi[idx + 1] = hi; g_xlo[idx + 1] = lo;
    split2(v.z, hi, lo); g_xhi[idx + 2] = hi; g_xlo[idx + 2] = lo;
    split2(v.w, hi, lo); g_xhi[idx + 3] = hi; g_xlo[idx + 3] = lo;
}

// ---------------- softmax over 40 cols (warp per row, in place) ------------
__global__ void k_softmax(float* __restrict__ C) {
    int warp = (blockIdx.x * blockDim.x + threadIdx.x) >> 5;
    int lane = threadIdx.x & 31;
    if (warp >= N_NODES) return;
    float* row = C + (size_t)warp * OUTD_F;
    float a0 = row[lane];
    float a1 = (lane + 32 < OUTD_F) ? row[lane + 32] : -1e30f;
    float m = fmaxf(a0, a1);
#pragma unroll
    for (int s = 16; s; s >>= 1) m = fmaxf(m, __shfl_xor_sync(0xFFFFFFFFu, m, s));
    float e0 = __expf(a0 - m);
    float e1 = (lane + 32 < OUTD_F) ? __expf(a1 - m) : 0.f;
    float sum = e0 + e1;
#pragma unroll
    for (int s = 16; s; s >>= 1) sum += __shfl_xor_sync(0xFFFFFFFFu, sum, s);
    float inv = 1.0f / sum;
    row[lane] = e0 * inv;
    if (lane + 32 < OUTD_F) row[lane + 32] = e1 * inv;
}

// ---------------- launch ----------------------------------------------------
extern "C" void kernel_launch(void* const* d_in, const int* in_sizes, int n_in,
                              void* d_out, int out_size) {
    const float* x   = (const float*)d_in[0];
    const int*   e32 = (const int*)d_in[1];
    const float* Wl0 = (const float*)d_in[2];
    const float* Wr0 = (const float*)d_in[3];
    const float* b0  = (const float*)d_in[4];
    const float* Wl1 = (const float*)d_in[5];
    const float* Wr1 = (const float*)d_in[6];
    const float* b1  = (const float*)d_in[7];
    const float* Wl2 = (const float*)d_in[8];
    const float* Wr2 = (const float*)d_in[9];
    const float* b2  = (const float*)d_in[10];
    float* out = (float*)d_out;

    const int TB = 256;
    int nblk_nodes = (N_NODES + TB - 1) / TB;
    int nblk_edges = (N_EDGES + TB - 1) / TB;
    int nblk_agg   = (N_NODES * 4 * 32 + TB - 1) / TB;
    int nblk_gemm  = (N_NODES + 127) / 128;            // 782
    int nblk_rows  = (N_NODES * 32 + TB - 1) / TB;

    // ---- dtype detect + build CSC ----
    k_detect<<<1, TB>>>(e32);
    k_zero_deg<<<nblk_nodes, TB>>>();
    k_hist<<<nblk_edges, TB>>>(e32);
    k_scan1<<<NB_SCAN, SCAN_B>>>();
    k_scan2<<<1, 1>>>();
    k_scan3<<<nblk_nodes, TB>>>();
    k_fill_csc<<<nblk_edges, TB>>>(e32);

    // ---- operand prep for layer 0 ----
    k_split_x<<<2048, TB>>>(x);
    k_split_w<<<(DIMF * DIMF + TB - 1) / TB, TB>>>(Wl0, Wr0, DIMF * DIMF);

    // ---- layer 0 ----
    k_agg<<<nblk_agg, TB>>>(x, 0);
    k_gemm_mma<128><<<nblk_gemm, TB>>>(b0, nullptr, 0);
    k_norm_relu_split<<<nblk_rows, TB>>>(0);

    // ---- layer 1 ----
    k_split_w<<<(DIMF * DIMF + TB - 1) / TB, TB>>>(Wl1, Wr1, DIMF * DIMF);
    k_agg<<<nblk_agg, TB>>>(nullptr, 1);
    k_gemm_mma<128><<<nblk_gemm, TB>>>(b1, nullptr, 1);
    k_norm_relu_split<<<nblk_rows, TB>>>(1);

    // ---- layer 2 + softmax ----
    k_split_w<<<(OUTD_F * DIMF + TB - 1) / TB, TB>>>(Wl2, Wr2, OUTD_F * DIMF);
    k_agg<<<nblk_agg, TB>>>(nullptr, 2);
    k_gemm_mma<40><<<nblk_gemm, TB>>>(b2, out, 2);
    k_softmax<<<nblk_rows, TB>>>(out);
}

// round 5
// speedup vs baseline: 1.4878x; 1.1640x over previous
#include <cuda_runtime.h>
#include <cuda_bf16.h>
#include <math.h>

#define N_NODES 100000
#define N_EDGES 1600000
#define DIMF    128
#define OUTD_F  40
#define SCAN_B  1024
#define NB_SCAN 98   // ceil(100000/1024)

// ---------------- scratch (device globals; no allocation allowed) ----------
__device__ int   g_is64;                 // 1 if edge_index stored as int64
__device__ int   g_deg[N_NODES];
__device__ float g_invdeg[N_NODES];
__device__ int   g_off[N_NODES + 1];
__device__ int   g_cursor[N_NODES];
__device__ int   g_bsums[NB_SCAN];
__device__ int   g_csc[N_EDGES];
__device__ __align__(16) float g_h0 [(size_t)N_NODES * DIMF];
__device__ __align__(16) float g_h1 [(size_t)N_NODES * DIMF];
__device__ __align__(16) float g_u  [(size_t)N_NODES * OUTD_F];  // h1 @ Wl2^T
__device__ __align__(16) float g_v  [(size_t)N_NODES * OUTD_F];  // h1 @ Wr2^T + b2
// bf16 split operands for tensor-core GEMM
__device__ __align__(16) __nv_bfloat16 g_agghi[(size_t)N_NODES * DIMF];
__device__ __align__(16) __nv_bfloat16 g_agglo[(size_t)N_NODES * DIMF];
__device__ __align__(16) __nv_bfloat16 g_xhi  [(size_t)N_NODES * DIMF];
__device__ __align__(16) __nv_bfloat16 g_xlo  [(size_t)N_NODES * DIMF];
__device__ __align__(16) __nv_bfloat16 g_Wlhi[DIMF * DIMF], g_Wllo[DIMF * DIMF];
__device__ __align__(16) __nv_bfloat16 g_Wrhi[DIMF * DIMF], g_Wrlo[DIMF * DIMF];

__device__ __forceinline__ const float* sel_src(int sel, const float* xin) {
    return sel == 0 ? xin : (sel == 1 ? g_h0 : g_h1);
}
__device__ __forceinline__ float* sel_dst(int sel, float* outp) {
    return sel == 0 ? g_h0 : (sel == 1 ? g_h1 : outp);
}

__device__ __forceinline__ int edge_at(const int* __restrict__ e32, int i) {
    return g_is64 ? e32[2 * i] : e32[i];
}

__device__ __forceinline__ void split2(float v, __nv_bfloat16& hi, __nv_bfloat16& lo) {
    hi = __float2bfloat16(v);
    lo = __float2bfloat16(v - __bfloat162float(hi));
}

// ---------------- dtype detection ------------------------------------------
__global__ void k_detect(const int* __restrict__ e32) {
    __shared__ int nonzero;
    if (threadIdx.x == 0) nonzero = 0;
    __syncthreads();
    for (int i = threadIdx.x; i < 1024; i += blockDim.x)
        if (e32[2 * i + 1] != 0) nonzero = 1;
    __syncthreads();
    if (threadIdx.x == 0) g_is64 = (nonzero == 0);
}

// ---------------- graph preprocessing --------------------------------------
__global__ void k_zero_deg() {
    int i = blockIdx.x * blockDim.x + threadIdx.x;
    if (i < N_NODES) g_deg[i] = 0;
}

__global__ void k_hist(const int* __restrict__ e32) {
    int e = blockIdx.x * blockDim.x + threadIdx.x;
    if (e < N_EDGES) {
        int d = edge_at(e32, N_EDGES + e);
        if ((unsigned)d < N_NODES) atomicAdd(&g_deg[d], 1);
    }
}

__global__ void k_scan1() {
    __shared__ int sh[SCAN_B];
    int t = threadIdx.x;
    int i = blockIdx.x * SCAN_B + t;
    int v = (i < N_NODES) ? g_deg[i] : 0;
    sh[t] = v;
    __syncthreads();
    for (int s = 1; s < SCAN_B; s <<= 1) {
        int prev = (t >= s) ? sh[t - s] : 0;
        __syncthreads();
        sh[t] += prev;
        __syncthreads();
    }
    if (i < N_NODES) g_off[i] = sh[t] - v;
    if (t == SCAN_B - 1) g_bsums[blockIdx.x] = sh[t];
}

__global__ void k_scan2() {
    int run = 0;
    for (int b = 0; b < NB_SCAN; b++) {
        int t = g_bsums[b];
        g_bsums[b] = run;
        run += t;
    }
}

__global__ void k_scan3() {
    int i = blockIdx.x * blockDim.x + threadIdx.x;
    if (i < N_NODES) {
        int o = g_off[i] + g_bsums[i >> 10];
        g_off[i] = o;
        g_cursor[i] = o;
        int d = g_deg[i];
        g_invdeg[i] = 1.0f / (float)(d > 1 ? d : 1);
    }
    if (i == 0) g_off[N_NODES] = N_EDGES;
}

__global__ void k_fill_csc(const int* __restrict__ e32) {
    int e = blockIdx.x * blockDim.x + threadIdx.x;
    if (e < N_EDGES) {
        int s = edge_at(e32, e);
        int d = edge_at(e32, N_EDGES + e);
        if ((unsigned)s < N_NODES && (unsigned)d < N_NODES) {
            int p = atomicAdd(&g_cursor[d], 1);
            g_csc[p] = s;
        }
    }
}

// ---------------- operand splitting -----------------------------------------
__global__ void k_split_x(const float* __restrict__ x) {
    for (size_t i = (size_t)blockIdx.x * blockDim.x + threadIdx.x;
         i < (size_t)N_NODES * DIMF; i += (size_t)gridDim.x * blockDim.x) {
        __nv_bfloat16 hi, lo; split2(x[i], hi, lo);
        g_xhi[i] = hi; g_xlo[i] = lo;
    }
}

__global__ void k_split_w(const float* __restrict__ Wl, const float* __restrict__ Wr, int n) {
    int i = blockIdx.x * blockDim.x + threadIdx.x;
    if (i < n) {
        __nv_bfloat16 hi, lo;
        split2(Wl[i], hi, lo); g_Wlhi[i] = hi; g_Wllo[i] = lo;
        split2(Wr[i], hi, lo); g_Wrhi[i] = hi; g_Wrlo[i] = lo;
    }
}

// combined W for layer 2: rows 0..39 = Wl2, rows 40..79 = Wr2 (into g_Wl*)
__global__ void k_split_w2(const float* __restrict__ Wl, const float* __restrict__ Wr) {
    int i = blockIdx.x * blockDim.x + threadIdx.x;
    int n = OUTD_F * DIMF;
    if (i < n) {
        __nv_bfloat16 hi, lo;
        split2(Wl[i], hi, lo); g_Wlhi[i] = hi; g_Wllo[i] = lo;
        split2(Wr[i], hi, lo); g_Wlhi[n + i] = hi; g_Wllo[n + i] = lo;
    }
}

// ---------------- mean aggregation (gather) -> bf16 split -------------------
__global__ void k_agg(const float* __restrict__ xin, int sel) {
    int warp = (blockIdx.x * blockDim.x + threadIdx.x) >> 5;
    int lane = threadIdx.x & 31;
    if (warp >= N_NODES * 4) return;
    const float* H = sel_src(sel, xin);
    int n = warp >> 2;
    int c = warp & 3;
    int base = c * 32 + lane;
    const float* Hp = H + base;
    int j = g_off[n], je = g_off[n + 1];
    float acc = 0.f;
    for (; j + 3 < je; j += 4) {
        int s0 = g_csc[j], s1 = g_csc[j + 1], s2 = g_csc[j + 2], s3 = g_csc[j + 3];
        float v0 = Hp[(size_t)s0 * DIMF];
        float v1 = Hp[(size_t)s1 * DIMF];
        float v2 = Hp[(size_t)s2 * DIMF];
        float v3 = Hp[(size_t)s3 * DIMF];
        acc += v0; acc += v1; acc += v2; acc += v3;
    }
    for (; j < je; j++) acc += Hp[(size_t)g_csc[j] * DIMF];
    float r = acc * g_invdeg[n];
    __nv_bfloat16 hi, lo; split2(r, hi, lo);
    size_t idx = (size_t)n * DIMF + base;
    g_agghi[idx] = hi; g_agglo[idx] = lo;
}

// ---------------- tensor-core GEMM pieces ----------------------------------
__device__ __forceinline__ void mma_bf16(float* d, const unsigned* a, unsigned b0, unsigned b1) {
    asm volatile(
        "mma.sync.aligned.m16n8k16.row.col.f32.bf16.bf16.f32 "
        "{%0,%1,%2,%3}, {%4,%5,%6,%7}, {%8,%9}, {%0,%1,%2,%3};\n"
        : "+f"(d[0]), "+f"(d[1]), "+f"(d[2]), "+f"(d[3])
        : "r"(a[0]), "r"(a[1]), "r"(a[2]), "r"(a[3]), "r"(b0), "r"(b1));
}

// layers 0/1: C = agg@Wl^T + X@Wr^T + b,  K = 256, OUTD = 128
__global__ void __launch_bounds__(256) k_gemm_mma(const float* __restrict__ bias,
                                                  float* __restrict__ outp, int selOut) {
    constexpr int OUTD = 128;
    constexpr int MT = 2, NT = 8, STR = 20;

    __shared__ __align__(16) unsigned sAh[128 * STR], sAl[128 * STR];
    __shared__ __align__(16) unsigned sWh[OUTD * STR], sWl[OUTD * STR];

    float* C = sel_dst(selOut, outp);
    int tid  = threadIdx.x;
    int wid  = tid >> 5, lane = tid & 31;
    int mw   = wid & 3, nw = wid >> 2;
    int row0 = blockIdx.x * 128;
    int lg   = lane >> 2, lt = lane & 3;

    float acc[MT][NT][4];
#pragma unroll
    for (int m = 0; m < MT; m++)
#pragma unroll
        for (int n = 0; n < NT; n++)
#pragma unroll
            for (int q = 0; q < 4; q++) acc[m][n][q] = 0.f;

#pragma unroll 1
    for (int kt = 0; kt < 8; kt++) {
        const unsigned* Ah = (const unsigned*)((kt < 4) ? g_agghi : g_xhi);
        const unsigned* Al = (const unsigned*)((kt < 4) ? g_agglo : g_xlo);
        const unsigned* Wh = (const unsigned*)((kt < 4) ? g_Wlhi : g_Wrhi);
        const unsigned* Wo = (const unsigned*)((kt < 4) ? g_Wllo : g_Wrlo);
        int kw = (kt & 3) * 16;

#pragma unroll
        for (int i = tid; i < 128 * 4; i += 256) {
            int r = i >> 2, q = (i & 3) * 4;
            uint4 vh = make_uint4(0, 0, 0, 0), vl = vh;
            if (row0 + r < N_NODES) {
                vh = *(const uint4*)(Ah + (size_t)(row0 + r) * 64 + kw + q);
                vl = *(const uint4*)(Al + (size_t)(row0 + r) * 64 + kw + q);
            }
            *(uint4*)(sAh + r * STR + q) = vh;
            *(uint4*)(sAl + r * STR + q) = vl;
        }
        for (int i = tid; i < OUTD * 4; i += 256) {
            int r = i >> 2, q = (i & 3) * 4;
            *(uint4*)(sWh + r * STR + q) = *(const uint4*)(Wh + (size_t)r * 64 + kw + q);
            *(uint4*)(sWl + r * STR + q) = *(const uint4*)(Wo + (size_t)r * 64 + kw + q);
        }
        __syncthreads();

#pragma unroll
        for (int ks = 0; ks < 2; ks++) {
            int wb = ks * 8;
            unsigned ah[MT][4], al[MT][4];
#pragma unroll
            for (int m = 0; m < MT; m++) {
                int rr = (mw * MT + m) * 16 + lg;
                ah[m][0] = sAh[rr * STR + wb + lt];
                ah[m][1] = sAh[(rr + 8) * STR + wb + lt];
                ah[m][2] = sAh[rr * STR + wb + 4 + lt];
                ah[m][3] = sAh[(rr + 8) * STR + wb + 4 + lt];
                al[m][0] = sAl[rr * STR + wb + lt];
                al[m][1] = sAl[(rr + 8) * STR + wb + lt];
                al[m][2] = sAl[rr * STR + wb + 4 + lt];
                al[m][3] = sAl[(rr + 8) * STR + wb + 4 + lt];
            }
#pragma unroll
            for (int n = 0; n < NT; n++) {
                int nr = nw * NT * 8 + n * 8 + lg;
                unsigned bh0 = sWh[nr * STR + wb + lt];
                unsigned bh1 = sWh[nr * STR + wb + 4 + lt];
                unsigned bl0 = sWl[nr * STR + wb + lt];
                unsigned bl1 = sWl[nr * STR + wb + 4 + lt];
#pragma unroll
                for (int m = 0; m < MT; m++) {
                    mma_bf16(acc[m][n], ah[m], bh0, bh1);
                    mma_bf16(acc[m][n], ah[m], bl0, bl1);
                    mma_bf16(acc[m][n], al[m], bh0, bh1);
                }
            }
        }
        __syncthreads();
    }

#pragma unroll
    for (int m = 0; m < MT; m++) {
        int r = row0 + (mw * MT + m) * 16 + lg;
#pragma unroll
        for (int n = 0; n < NT; n++) {
            int c = nw * NT * 8 + n * 8 + lt * 2;
            float bv0 = bias[c], bv1 = bias[c + 1];
            if (r < N_NODES) {
                C[(size_t)r * OUTD + c]     = acc[m][n][0] + bv0;
                C[(size_t)r * OUTD + c + 1] = acc[m][n][1] + bv1;
            }
            if (r + 8 < N_NODES) {
                C[(size_t)(r + 8) * OUTD + c]     = acc[m][n][2] + bv0;
                C[(size_t)(r + 8) * OUTD + c + 1] = acc[m][n][3] + bv1;
            }
        }
    }
}

// layer 2: [u|v] = h1 @ [Wl2;Wr2]^T, K = 128, 80 output cols
// u = cols 0..39 (no bias), v = cols 40..79 (+bias)
__global__ void __launch_bounds__(256) k_gemm2(const float* __restrict__ bias) {
    constexpr int OUTD = 80;
    constexpr int MT = 2, NT = 5, STR = 20;

    __shared__ __align__(16) unsigned sAh[128 * STR], sAl[128 * STR];
    __shared__ __align__(16) unsigned sWh[OUTD * STR], sWl[OUTD * STR];

    int tid  = threadIdx.x;
    int wid  = tid >> 5, lane = tid & 31;
    int mw   = wid & 3, nw = wid >> 2;
    int row0 = blockIdx.x * 128;
    int lg   = lane >> 2, lt = lane & 3;

    float acc[MT][NT][4];
#pragma unroll
    for (int m = 0; m < MT; m++)
#pragma unroll
        for (int n = 0; n < NT; n++)
#pragma unroll
            for (int q = 0; q < 4; q++) acc[m][n][q] = 0.f;

    const unsigned* Ah = (const unsigned*)g_xhi;   // h1 split
    const unsigned* Al = (const unsigned*)g_xlo;
    const unsigned* Wh = (const unsigned*)g_Wlhi;  // combined 80x128
    const unsigned* Wo = (const unsigned*)g_Wllo;

#pragma unroll 1
    for (int kt = 0; kt < 4; kt++) {
        int kw = kt * 16;

#pragma unroll
        for (int i = tid; i < 128 * 4; i += 256) {
            int r = i >> 2, q = (i & 3) * 4;
            uint4 vh = make_uint4(0, 0, 0, 0), vl = vh;
            if (row0 + r < N_NODES) {
                vh = *(const uint4*)(Ah + (size_t)(row0 + r) * 64 + kw + q);
                vl = *(const uint4*)(Al + (size_t)(row0 + r) * 64 + kw + q);
            }
            *(uint4*)(sAh + r * STR + q) = vh;
            *(uint4*)(sAl + r * STR + q) = vl;
        }
        for (int i = tid; i < OUTD * 4; i += 256) {
            int r = i >> 2, q = (i & 3) * 4;
            *(uint4*)(sWh + r * STR + q) = *(const uint4*)(Wh + (size_t)r * 64 + kw + q);
            *(uint4*)(sWl + r * STR + q) = *(const uint4*)(Wo + (size_t)r * 64 + kw + q);
        }
        __syncthreads();

#pragma unroll
        for (int ks = 0; ks < 2; ks++) {
            int wb = ks * 8;
            unsigned ah[MT][4], al[MT][4];
#pragma unroll
            for (int m = 0; m < MT; m++) {
                int rr = (mw * MT + m) * 16 + lg;
                ah[m][0] = sAh[rr * STR + wb + lt];
                ah[m][1] = sAh[(rr + 8) * STR + wb + lt];
                ah[m][2] = sAh[rr * STR + wb + 4 + lt];
                ah[m][3] = sAh[(rr + 8) * STR + wb + 4 + lt];
                al[m][0] = sAl[rr * STR + wb + lt];
                al[m][1] = sAl[(rr + 8) * STR + wb + lt];
                al[m][2] = sAl[rr * STR + wb + 4 + lt];
                al[m][3] = sAl[(rr + 8) * STR + wb + 4 + lt];
            }
#pragma unroll
            for (int n = 0; n < NT; n++) {
                int nr = nw * NT * 8 + n * 8 + lg;
                unsigned bh0 = sWh[nr * STR + wb + lt];
                unsigned bh1 = sWh[nr * STR + wb + 4 + lt];
                unsigned bl0 = sWl[nr * STR + wb + lt];
                unsigned bl1 = sWl[nr * STR + wb + 4 + lt];
#pragma unroll
                for (int m = 0; m < MT; m++) {
                    mma_bf16(acc[m][n], ah[m], bh0, bh1);
                    mma_bf16(acc[m][n], ah[m], bl0, bl1);
                    mma_bf16(acc[m][n], al[m], bh0, bh1);
                }
            }
        }
        __syncthreads();
    }

#pragma unroll
    for (int m = 0; m < MT; m++) {
        int r = row0 + (mw * MT + m) * 16 + lg;
#pragma unroll
        for (int n = 0; n < NT; n++) {
            int c = nw * NT * 8 + n * 8 + lt * 2;
#pragma unroll
            for (int h = 0; h < 2; h++) {
                int rr = r + h * 8;
                if (rr >= N_NODES) continue;
                float v0 = acc[m][n][h * 2], v1 = acc[m][n][h * 2 + 1];
                if (c < OUTD_F) {
                    g_u[(size_t)rr * OUTD_F + c]     = v0;
                    g_u[(size_t)rr * OUTD_F + c + 1] = v1;
                } else {
                    g_v[(size_t)rr * OUTD_F + c - OUTD_F]     = v0 + bias[c - OUTD_F];
                    g_v[(size_t)rr * OUTD_F + c - OUTD_F + 1] = v1 + bias[c - OUTD_F + 1];
                }
            }
        }
    }
}

// ---------------- L2-normalize + ReLU + bf16 split (warp per row) ----------
__global__ void k_norm_relu_split(int sel) {
    int warp = (blockIdx.x * blockDim.x + threadIdx.x) >> 5;
    int lane = threadIdx.x & 31;
    if (warp >= N_NODES) return;
    float* H = sel == 0 ? g_h0 : g_h1;
    float4* p = (float4*)(H + (size_t)warp * DIMF + lane * 4);
    float4 v = *p;
    float ss = v.x * v.x + v.y * v.y + v.z * v.z + v.w * v.w;
#pragma unroll
    for (int s = 16; s; s >>= 1) ss += __shfl_xor_sync(0xFFFFFFFFu, ss, s);
    float sc = 1.0f / fmaxf(sqrtf(ss), 1e-12f);
    v.x = fmaxf(v.x * sc, 0.f);
    v.y = fmaxf(v.y * sc, 0.f);
    v.z = fmaxf(v.z * sc, 0.f);
    v.w = fmaxf(v.w * sc, 0.f);
    *p = v;
    size_t idx = (size_t)warp * DIMF + lane * 4;
    __nv_bfloat16 hi, lo;
    split2(v.x, hi, lo); g_xhi[idx]     = hi; g_xlo[idx]     = lo;
    split2(v.y, hi, lo); g_xhi[idx + 1] = hi; g_xlo[idx + 1] = lo;
    split2(v.z, hi, lo); g_xhi[idx + 2] = hi; g_xlo[idx + 2] = lo;
    split2(v.w, hi, lo); g_xhi[idx + 3] = hi; g_xlo[idx + 3] = lo;
}

// ---------------- layer-2: gather u, add v, softmax (warp per node) --------
__global__ void k_agg_softmax(float* __restrict__ out) {
    int warp = (blockIdx.x * blockDim.x + threadIdx.x) >> 5;
    int lane = threadIdx.x & 31;
    if (warp >= N_NODES) return;
    int n = warp;
    int j = g_off[n], je = g_off[n + 1];
    float acc0 = 0.f, acc1 = 0.f;
    for (; j + 1 < je; j += 2) {
        int s0 = g_csc[j], s1 = g_csc[j + 1];
        const float* u0 = g_u + (size_t)s0 * OUTD_F;
        const float* u1 = g_u + (size_t)s1 * OUTD_F;
        acc0 += u0[lane];
        acc0 += u1[lane];
        if (lane < 8) { acc1 += u0[32 + lane]; acc1 += u1[32 + lane]; }
    }
    if (j < je) {
        const float* u0 = g_u + (size_t)g_csc[j] * OUTD_F;
        acc0 += u0[lane];
        if (lane < 8) acc1 += u0[32 + lane];
    }
    float inv_d = g_invdeg[n];
    const float* vp = g_v + (size_t)n * OUTD_F;
    float a0 = acc0 * inv_d + vp[lane];
    float a1 = (lane < 8) ? (acc1 * inv_d + vp[32 + lane]) : -1e30f;

    float m = fmaxf(a0, a1);
#pragma unroll
    for (int s = 16; s; s >>= 1) m = fmaxf(m, __shfl_xor_sync(0xFFFFFFFFu, m, s));
    float e0 = __expf(a0 - m);
    float e1 = (lane < 8) ? __expf(a1 - m) : 0.f;
    float sum = e0 + e1;
#pragma unroll
    for (int s = 16; s; s >>= 1) sum += __shfl_xor_sync(0xFFFFFFFFu, sum, s);
    float inv = 1.0f / sum;
    float* row = out + (size_t)n * OUTD_F;
    row[lane] = e0 * inv;
    if (lane < 8) row[32 + lane] = e1 * inv;
}

// ---------------- launch ----------------------------------------------------
extern "C" void kernel_launch(void* const* d_in, const int* in_sizes, int n_in,
                              void* d_out, int out_size) {
    const float* x   = (const float*)d_in[0];
    const int*   e32 = (const int*)d_in[1];
    const float* Wl0 = (const float*)d_in[2];
    const float* Wr0 = (const float*)d_in[3];
    const float* b0  = (const float*)d_in[4];
    const float* Wl1 = (const float*)d_in[5];
    const float* Wr1 = (const float*)d_in[6];
    const float* b1  = (const float*)d_in[7];
    const float* Wl2 = (const float*)d_in[8];
    const float* Wr2 = (const float*)d_in[9];
    const float* b2  = (const float*)d_in[10];
    float* out = (float*)d_out;

    const int TB = 256;
    int nblk_nodes = (N_NODES + TB - 1) / TB;
    int nblk_edges = (N_EDGES + TB - 1) / TB;
    int nblk_agg   = (N_NODES * 4 * 32 + TB - 1) / TB;
    int nblk_gemm  = (N_NODES + 127) / 128;            // 782
    int nblk_rows  = (N_NODES * 32 + TB - 1) / TB;

    // ---- dtype detect + build CSC ----
    k_detect<<<1, TB>>>(e32);
    k_zero_deg<<<nblk_nodes, TB>>>();
    k_hist<<<nblk_edges, TB>>>(e32);
    k_scan1<<<NB_SCAN, SCAN_B>>>();
    k_scan2<<<1, 1>>>();
    k_scan3<<<nblk_nodes, TB>>>();
    k_fill_csc<<<nblk_edges, TB>>>(e32);

    // ---- operand prep for layer 0 ----
    k_split_x<<<2048, TB>>>(x);
    k_split_w<<<(DIMF * DIMF + TB - 1) / TB, TB>>>(Wl0, Wr0, DIMF * DIMF);

    // ---- layer 0 ----
    k_agg<<<nblk_agg, TB>>>(x, 0);
    k_gemm_mma<<<nblk_gemm, TB>>>(b0, nullptr, 0);
    k_norm_relu_split<<<nblk_rows, TB>>>(0);

    // ---- layer 1 ----
    k_split_w<<<(DIMF * DIMF + TB - 1) / TB, TB>>>(Wl1, Wr1, DIMF * DIMF);
    k_agg<<<nblk_agg, TB>>>(nullptr, 1);
    k_gemm_mma<<<nblk_gemm, TB>>>(b1, nullptr, 1);
    k_norm_relu_split<<<nblk_rows, TB>>>(1);

    // ---- layer 2 (linearity: project first, then aggregate 40-dim) ----
    k_split_w2<<<(OUTD_F * DIMF + TB - 1) / TB, TB>>>(Wl2, Wr2);
    k_gemm2<<<nblk_gemm, TB>>>(b2);
    k_agg_softmax<<<(N_NODES + 7) / 8, TB>>>(out);
}

// round 6
// speedup vs baseline: 1.9908x; 1.3380x over previous
#include <cuda_runtime.h>
#include <cuda_bf16.h>
#include <math.h>

#define N_NODES 100000
#define N_EDGES 1600000
#define DIMF    128
#define OUTD_F  40
#define SCAN_B  1024
#define NB_SCAN 98   // ceil(100000/1024)

// ---------------- scratch (device globals; no allocation allowed) ----------
__device__ int   g_is64;                 // 1 if edge_index stored as int64
__device__ int   g_deg[N_NODES];
__device__ float g_invdeg[N_NODES];
__device__ int   g_off[N_NODES + 1];
__device__ int   g_cursor[N_NODES];
__device__ int   g_bsums[NB_SCAN];
__device__ int   g_csc[N_EDGES];
__device__ __align__(16) float g_U [(size_t)N_NODES * DIMF];   // X @ Wl^T
__device__ __align__(16) float g_V [(size_t)N_NODES * DIMF];   // X @ Wr^T + b
__device__ __align__(16) float g_u  [(size_t)N_NODES * OUTD_F]; // layer2: h1 @ Wl2^T
__device__ __align__(16) float g_v  [(size_t)N_NODES * OUTD_F]; // layer2: h1 @ Wr2^T + b2
// bf16 split operands for tensor-core GEMM
__device__ __align__(16) __nv_bfloat16 g_xhi  [(size_t)N_NODES * DIMF];
__device__ __align__(16) __nv_bfloat16 g_xlo  [(size_t)N_NODES * DIMF];
__device__ __align__(16) __nv_bfloat16 g_Wlhi[DIMF * DIMF], g_Wllo[DIMF * DIMF];
__device__ __align__(16) __nv_bfloat16 g_Wrhi[DIMF * DIMF], g_Wrlo[DIMF * DIMF];

__device__ __forceinline__ int edge_at(const int* __restrict__ e32, int i) {
    return g_is64 ? e32[2 * i] : e32[i];
}

__device__ __forceinline__ void split2(float v, __nv_bfloat16& hi, __nv_bfloat16& lo) {
    hi = __float2bfloat16(v);
    lo = __float2bfloat16(v - __bfloat162float(hi));
}

// ---------------- dtype detection ------------------------------------------
__global__ void k_detect(const int* __restrict__ e32) {
    __shared__ int nonzero;
    if (threadIdx.x == 0) nonzero = 0;
    __syncthreads();
    for (int i = threadIdx.x; i < 1024; i += blockDim.x)
        if (e32[2 * i + 1] != 0) nonzero = 1;
    __syncthreads();
    if (threadIdx.x == 0) g_is64 = (nonzero == 0);
}

// ---------------- graph preprocessing --------------------------------------
__global__ void k_zero_deg() {
    int i = blockIdx.x * blockDim.x + threadIdx.x;
    if (i < N_NODES) g_deg[i] = 0;
}

__global__ void k_hist(const int* __restrict__ e32) {
    int e = blockIdx.x * blockDim.x + threadIdx.x;
    if (e < N_EDGES) {
        int d = edge_at(e32, N_EDGES + e);
        if ((unsigned)d < N_NODES) atomicAdd(&g_deg[d], 1);
    }
}

__global__ void k_scan1() {
    __shared__ int sh[SCAN_B];
    int t = threadIdx.x;
    int i = blockIdx.x * SCAN_B + t;
    int v = (i < N_NODES) ? g_deg[i] : 0;
    sh[t] = v;
    __syncthreads();
    for (int s = 1; s < SCAN_B; s <<= 1) {
        int prev = (t >= s) ? sh[t - s] : 0;
        __syncthreads();
        sh[t] += prev;
        __syncthreads();
    }
    if (i < N_NODES) g_off[i] = sh[t] - v;
    if (t == SCAN_B - 1) g_bsums[blockIdx.x] = sh[t];
}

__global__ void k_scan2() {
    int run = 0;
    for (int b = 0; b < NB_SCAN; b++) {
        int t = g_bsums[b];
        g_bsums[b] = run;
        run += t;
    }
}

__global__ void k_scan3() {
    int i = blockIdx.x * blockDim.x + threadIdx.x;
    if (i < N_NODES) {
        int o = g_off[i] + g_bsums[i >> 10];
        g_off[i] = o;
        g_cursor[i] = o;
        int d = g_deg[i];
        g_invdeg[i] = 1.0f / (float)(d > 1 ? d : 1);
    }
    if (i == 0) g_off[N_NODES] = N_EDGES;
}

__global__ void k_fill_csc(const int* __restrict__ e32) {
    int e = blockIdx.x * blockDim.x + threadIdx.x;
    if (e < N_EDGES) {
        int s = edge_at(e32, e);
        int d = edge_at(e32, N_EDGES + e);
        if ((unsigned)s < N_NODES && (unsigned)d < N_NODES) {
            int p = atomicAdd(&g_cursor[d], 1);
            g_csc[p] = s;
        }
    }
}

// ---------------- operand splitting -----------------------------------------
__global__ void k_split_x(const float* __restrict__ x) {
    for (size_t i = (size_t)blockIdx.x * blockDim.x + threadIdx.x;
         i < (size_t)N_NODES * DIMF; i += (size_t)gridDim.x * blockDim.x) {
        __nv_bfloat16 hi, lo; split2(x[i], hi, lo);
        g_xhi[i] = hi; g_xlo[i] = lo;
    }
}

__global__ void k_split_w(const float* __restrict__ Wl, const float* __restrict__ Wr, int n) {
    int i = blockIdx.x * blockDim.x + threadIdx.x;
    if (i < n) {
        __nv_bfloat16 hi, lo;
        split2(Wl[i], hi, lo); g_Wlhi[i] = hi; g_Wllo[i] = lo;
        split2(Wr[i], hi, lo); g_Wrhi[i] = hi; g_Wrlo[i] = lo;
    }
}

// combined W for layer 2: rows 0..39 = Wl2, rows 40..79 = Wr2 (into g_Wl*)
__global__ void k_split_w2(const float* __restrict__ Wl, const float* __restrict__ Wr) {
    int i = blockIdx.x * blockDim.x + threadIdx.x;
    int n = OUTD_F * DIMF;
    if (i < n) {
        __nv_bfloat16 hi, lo;
        split2(Wl[i], hi, lo); g_Wlhi[i] = hi; g_Wllo[i] = lo;
        split2(Wr[i], hi, lo); g_Wlhi[n + i] = hi; g_Wllo[n + i] = lo;
    }
}

// ---------------- tensor-core GEMM pieces ----------------------------------
__device__ __forceinline__ void mma_bf16(float* d, const unsigned* a, unsigned b0, unsigned b1) {
    asm volatile(
        "mma.sync.aligned.m16n8k16.row.col.f32.bf16.bf16.f32 "
        "{%0,%1,%2,%3}, {%4,%5,%6,%7}, {%8,%9}, {%0,%1,%2,%3};\n"
        : "+f"(d[0]), "+f"(d[1]), "+f"(d[2]), "+f"(d[3])
        : "r"(a[0]), "r"(a[1]), "r"(a[2]), "r"(a[3]), "r"(b0), "r"(b1));
}

// layers 0/1: blockIdx.y==0 -> U = X@Wl^T ; blockIdx.y==1 -> V = X@Wr^T + b
__global__ void __launch_bounds__(256) k_gemm_l01(const float* __restrict__ bias) {
    constexpr int OUTD = 128;
    constexpr int MT = 2, NT = 8, STR = 20;

    __shared__ __align__(16) unsigned sAh[128 * STR], sAl[128 * STR];
    __shared__ __align__(16) unsigned sWh[OUTD * STR], sWl[OUTD * STR];

    int side = blockIdx.y;
    const unsigned* Ah = (const unsigned*)g_xhi;
    const unsigned* Al = (const unsigned*)g_xlo;
    const unsigned* Wh = (const unsigned*)(side ? g_Wrhi : g_Wlhi);
    const unsigned* Wo = (const unsigned*)(side ? g_Wrlo : g_Wllo);
    float* C = side ? g_V : g_U;

    int tid  = threadIdx.x;
    int wid  = tid >> 5, lane = tid & 31;
    int mw   = wid & 3, nw = wid >> 2;
    int row0 = blockIdx.x * 128;
    int lg   = lane >> 2, lt = lane & 3;

    float acc[MT][NT][4];
#pragma unroll
    for (int m = 0; m < MT; m++)
#pragma unroll
        for (int n = 0; n < NT; n++)
#pragma unroll
            for (int q = 0; q < 4; q++) acc[m][n][q] = 0.f;

#pragma unroll 1
    for (int kt = 0; kt < 4; kt++) {
        int kw = kt * 16;

#pragma unroll
        for (int i = tid; i < 128 * 4; i += 256) {
            int r = i >> 2, q = (i & 3) * 4;
            uint4 vh = make_uint4(0, 0, 0, 0), vl = vh;
            if (row0 + r < N_NODES) {
                vh = *(const uint4*)(Ah + (size_t)(row0 + r) * 64 + kw + q);
                vl = *(const uint4*)(Al + (size_t)(row0 + r) * 64 + kw + q);
            }
            *(uint4*)(sAh + r * STR + q) = vh;
            *(uint4*)(sAl + r * STR + q) = vl;
        }
        for (int i = tid; i < OUTD * 4; i += 256) {
            int r = i >> 2, q = (i & 3) * 4;
            *(uint4*)(sWh + r * STR + q) = *(const uint4*)(Wh + (size_t)r * 64 + kw + q);
            *(uint4*)(sWl + r * STR + q) = *(const uint4*)(Wo + (size_t)r * 64 + kw + q);
        }
        __syncthreads();

#pragma unroll
        for (int ks = 0; ks < 2; ks++) {
            int wb = ks * 8;
            unsigned ah[MT][4], al[MT][4];
#pragma unroll
            for (int m = 0; m < MT; m++) {
                int rr = (mw * MT + m) * 16 + lg;
                ah[m][0] = sAh[rr * STR + wb + lt];
                ah[m][1] = sAh[(rr + 8) * STR + wb + lt];
                ah[m][2] = sAh[rr * STR + wb + 4 + lt];
                ah[m][3] = sAh[(rr + 8) * STR + wb + 4 + lt];
                al[m][0] = sAl[rr * STR + wb + lt];
                al[m][1] = sAl[(rr + 8) * STR + wb + lt];
                al[m][2] = sAl[rr * STR + wb + 4 + lt];
                al[m][3] = sAl[(rr + 8) * STR + wb + 4 + lt];
            }
#pragma unroll
            for (int n = 0; n < NT; n++) {
                int nr = nw * NT * 8 + n * 8 + lg;
                unsigned bh0 = sWh[nr * STR + wb + lt];
                unsigned bh1 = sWh[nr * STR + wb + 4 + lt];
                unsigned bl0 = sWl[nr * STR + wb + lt];
                unsigned bl1 = sWl[nr * STR + wb + 4 + lt];
#pragma unroll
                for (int m = 0; m < MT; m++) {
                    mma_bf16(acc[m][n], ah[m], bh0, bh1);
                    mma_bf16(acc[m][n], ah[m], bl0, bl1);
                    mma_bf16(acc[m][n], al[m], bh0, bh1);
                }
            }
        }
        __syncthreads();
    }

#pragma unroll
    for (int m = 0; m < MT; m++) {
        int r = row0 + (mw * MT + m) * 16 + lg;
#pragma unroll
        for (int n = 0; n < NT; n++) {
            int c = nw * NT * 8 + n * 8 + lt * 2;
            float bv0 = side ? bias[c] : 0.f;
            float bv1 = side ? bias[c + 1] : 0.f;
            if (r < N_NODES) {
                C[(size_t)r * OUTD + c]     = acc[m][n][0] + bv0;
                C[(size_t)r * OUTD + c + 1] = acc[m][n][1] + bv1;
            }
            if (r + 8 < N_NODES) {
                C[(size_t)(r + 8) * OUTD + c]     = acc[m][n][2] + bv0;
                C[(size_t)(r + 8) * OUTD + c + 1] = acc[m][n][3] + bv1;
            }
        }
    }
}

// layer 2: [u|v] = h1 @ [Wl2;Wr2]^T, K = 128, 80 output cols
__global__ void __launch_bounds__(256) k_gemm2(const float* __restrict__ bias) {
    constexpr int OUTD = 80;
    constexpr int MT = 2, NT = 5, STR = 20;

    __shared__ __align__(16) unsigned sAh[128 * STR], sAl[128 * STR];
    __shared__ __align__(16) unsigned sWh[OUTD * STR], sWl[OUTD * STR];

    int tid  = threadIdx.x;
    int wid  = tid >> 5, lane = tid & 31;
    int mw   = wid & 3, nw = wid >> 2;
    int row0 = blockIdx.x * 128;
    int lg   = lane >> 2, lt = lane & 3;

    float acc[MT][NT][4];
#pragma unroll
    for (int m = 0; m < MT; m++)
#pragma unroll
        for (int n = 0; n < NT; n++)
#pragma unroll
            for (int q = 0; q < 4; q++) acc[m][n][q] = 0.f;

    const unsigned* Ah = (const unsigned*)g_xhi;   // h1 split
    const unsigned* Al = (const unsigned*)g_xlo;
    const unsigned* Wh = (const unsigned*)g_Wlhi;  // combined 80x128
    const unsigned* Wo = (const unsigned*)g_Wllo;

#pragma unroll 1
    for (int kt = 0; kt < 4; kt++) {
        int kw = kt * 16;

#pragma unroll
        for (int i = tid; i < 128 * 4; i += 256) {
            int r = i >> 2, q = (i & 3) * 4;
            uint4 vh = make_uint4(0, 0, 0, 0), vl = vh;
            if (row0 + r < N_NODES) {
                vh = *(const uint4*)(Ah + (size_t)(row0 + r) * 64 + kw + q);
                vl = *(const uint4*)(Al + (size_t)(row0 + r) * 64 + kw + q);
            }
            *(uint4*)(sAh + r * STR + q) = vh;
            *(uint4*)(sAl + r * STR + q) = vl;
        }
        for (int i = tid; i < OUTD * 4; i += 256) {
            int r = i >> 2, q = (i & 3) * 4;
            *(uint4*)(sWh + r * STR + q) = *(const uint4*)(Wh + (size_t)r * 64 + kw + q);
            *(uint4*)(sWl + r * STR + q) = *(const uint4*)(Wo + (size_t)r * 64 + kw + q);
        }
        __syncthreads();

#pragma unroll
        for (int ks = 0; ks < 2; ks++) {
            int wb = ks * 8;
            unsigned ah[MT][4], al[MT][4];
#pragma unroll
            for (int m = 0; m < MT; m++) {
                int rr = (mw * MT + m) * 16 + lg;
                ah[m][0] = sAh[rr * STR + wb + lt];
                ah[m][1] = sAh[(rr + 8) * STR + wb + lt];
                ah[m][2] = sAh[rr * STR + wb + 4 + lt];
                ah[m][3] = sAh[(rr + 8) * STR + wb + 4 + lt];
                al[m][0] = sAl[rr * STR + wb + lt];
                al[m][1] = sAl[(rr + 8) * STR + wb + lt];
                al[m][2] = sAl[rr * STR + wb + 4 + lt];
                al[m][3] = sAl[(rr + 8) * STR + wb + 4 + lt];
            }
#pragma unroll
            for (int n = 0; n < NT; n++) {
                int nr = nw * NT * 8 + n * 8 + lg;
                unsigned bh0 = sWh[nr * STR + wb + lt];
                unsigned bh1 = sWh[nr * STR + wb + 4 + lt];
                unsigned bl0 = sWl[nr * STR + wb + lt];
                unsigned bl1 = sWl[nr * STR + wb + 4 + lt];
#pragma unroll
                for (int m = 0; m < MT; m++) {
                    mma_bf16(acc[m][n], ah[m], bh0, bh1);
                    mma_bf16(acc[m][n], ah[m], bl0, bl1);
                    mma_bf16(acc[m][n], al[m], bh0, bh1);
                }
            }
        }
        __syncthreads();
    }

#pragma unroll
    for (int m = 0; m < MT; m++) {
        int r = row0 + (mw * MT + m) * 16 + lg;
#pragma unroll
        for (int n = 0; n < NT; n++) {
            int c = nw * NT * 8 + n * 8 + lt * 2;
#pragma unroll
            for (int h = 0; h < 2; h++) {
                int rr = r + h * 8;
                if (rr >= N_NODES) continue;
                float v0 = acc[m][n][h * 2], v1 = acc[m][n][h * 2 + 1];
                if (c < OUTD_F) {
                    g_u[(size_t)rr * OUTD_F + c]     = v0;
                    g_u[(size_t)rr * OUTD_F + c + 1] = v1;
                } else {
                    g_v[(size_t)rr * OUTD_F + c - OUTD_F]     = v0 + bias[c - OUTD_F];
                    g_v[(size_t)rr * OUTD_F + c - OUTD_F + 1] = v1 + bias[c - OUTD_F + 1];
                }
            }
        }
    }
}

// ---------------- fused: gather-mean(U) + V, L2-norm, ReLU, bf16 split -----
// one warp per node, float4 per lane (128 dims).
__global__ void k_aggnorm() {
    int warp = (blockIdx.x * blockDim.x + threadIdx.x) >> 5;
    int lane = threadIdx.x & 31;
    if (warp >= N_NODES) return;
    int n = warp;
    const float4* U4 = (const float4*)g_U;
    int j = g_off[n], je = g_off[n + 1];
    float ax = 0.f, ay = 0.f, az = 0.f, aw = 0.f;
    for (; j + 1 < je; j += 2) {
        int s0 = g_csc[j], s1 = g_csc[j + 1];
        float4 v0 = U4[(size_t)s0 * 32 + lane];
        float4 v1 = U4[(size_t)s1 * 32 + lane];
        ax += v0.x + v1.x;
        ay += v0.y + v1.y;
        az += v0.z + v1.z;
        aw += v0.w + v1.w;
    }
    if (j < je) {
        float4 v0 = U4[(size_t)g_csc[j] * 32 + lane];
        ax += v0.x; ay += v0.y; az += v0.z; aw += v0.w;
    }
    float inv_d = g_invdeg[n];
    float4 vv = ((const float4*)g_V)[(size_t)n * 32 + lane];
    ax = ax * inv_d + vv.x;
    ay = ay * inv_d + vv.y;
    az = az * inv_d + vv.z;
    aw = aw * inv_d + vv.w;

    float ss = ax * ax + ay * ay + az * az + aw * aw;
#pragma unroll
    for (int s = 16; s; s >>= 1) ss += __shfl_xor_sync(0xFFFFFFFFu, ss, s);
    float sc = 1.0f / fmaxf(sqrtf(ss), 1e-12f);
    ax = fmaxf(ax * sc, 0.f);
    ay = fmaxf(ay * sc, 0.f);
    az = fmaxf(az * sc, 0.f);
    aw = fmaxf(aw * sc, 0.f);

    size_t idx = (size_t)n * DIMF + lane * 4;
    __nv_bfloat16 hi, lo;
    split2(ax, hi, lo); g_xhi[idx]     = hi; g_xlo[idx]     = lo;
    split2(ay, hi, lo); g_xhi[idx + 1] = hi; g_xlo[idx + 1] = lo;
    split2(az, hi, lo); g_xhi[idx + 2] = hi; g_xlo[idx + 2] = lo;
    split2(aw, hi, lo); g_xhi[idx + 3] = hi; g_xlo[idx + 3] = lo;
}

// ---------------- layer-2: gather u, add v, softmax (warp per node) --------
__global__ void k_agg_softmax(float* __restrict__ out) {
    int warp = (blockIdx.x * blockDim.x + threadIdx.x) >> 5;
    int lane = threadIdx.x & 31;
    if (warp >= N_NODES) return;
    int n = warp;
    int j = g_off[n], je = g_off[n + 1];
    float acc0 = 0.f, acc1 = 0.f;
    for (; j + 1 < je; j += 2) {
        int s0 = g_csc[j], s1 = g_csc[j + 1];
        const float* u0 = g_u + (size_t)s0 * OUTD_F;
        const float* u1 = g_u + (size_t)s1 * OUTD_F;
        acc0 += u0[lane];
        acc0 += u1[lane];
        if (lane < 8) { acc1 += u0[32 + lane]; acc1 += u1[32 + lane]; }
    }
    if (j < je) {
        const float* u0 = g_u + (size_t)g_csc[j] * OUTD_F;
        acc0 += u0[lane];
        if (lane < 8) acc1 += u0[32 + lane];
    }
    float inv_d = g_invdeg[n];
    const float* vp = g_v + (size_t)n * OUTD_F;
    float a0 = acc0 * inv_d + vp[lane];
    float a1 = (lane < 8) ? (acc1 * inv_d + vp[32 + lane]) : -1e30f;

    float m = fmaxf(a0, a1);
#pragma unroll
    for (int s = 16; s; s >>= 1) m = fmaxf(m, __shfl_xor_sync(0xFFFFFFFFu, m, s));
    float e0 = __expf(a0 - m);
    float e1 = (lane < 8) ? __expf(a1 - m) : 0.f;
    float sum = e0 + e1;
#pragma unroll
    for (int s = 16; s; s >>= 1) sum += __shfl_xor_sync(0xFFFFFFFFu, sum, s);
    float inv = 1.0f / sum;
    float* row = out + (size_t)n * OUTD_F;
    row[lane] = e0 * inv;
    if (lane < 8) row[32 + lane] = e1 * inv;
}

// ---------------- launch ----------------------------------------------------
extern "C" void kernel_launch(void* const* d_in, const int* in_sizes, int n_in,
                              void* d_out, int out_size) {
    const float* x   = (const float*)d_in[0];
    const int*   e32 = (const int*)d_in[1];
    const float* Wl0 = (const float*)d_in[2];
    const float* Wr0 = (const float*)d_in[3];
    const float* b0  = (const float*)d_in[4];
    const float* Wl1 = (const float*)d_in[5];
    const float* Wr1 = (const float*)d_in[6];
    const float* b1  = (const float*)d_in[7];
    const float* Wl2 = (const float*)d_in[8];
    const float* Wr2 = (const float*)d_in[9];
    const float* b2  = (const float*)d_in[10];
    float* out = (float*)d_out;

    const int TB = 256;
    int nblk_nodes = (N_NODES + TB - 1) / TB;
    int nblk_edges = (N_EDGES + TB - 1) / TB;
    int nblk_gemm  = (N_NODES + 127) / 128;            // 782
    int nblk_wnode = (N_NODES + 7) / 8;                // warp-per-node, 8 warps/blk

    // ---- dtype detect + build CSC ----
    k_detect<<<1, TB>>>(e32);
    k_zero_deg<<<nblk_nodes, TB>>>();
    k_hist<<<nblk_edges, TB>>>(e32);
    k_scan1<<<NB_SCAN, SCAN_B>>>();
    k_scan2<<<1, 1>>>();
    k_scan3<<<nblk_nodes, TB>>>();
    k_fill_csc<<<nblk_edges, TB>>>(e32);

    // ---- operand prep for layer 0 ----
    k_split_x<<<2048, TB>>>(x);
    k_split_w<<<(DIMF * DIMF + TB - 1) / TB, TB>>>(Wl0, Wr0, DIMF * DIMF);

    // ---- layer 0: U=x@Wl0^T, V=x@Wr0^T+b0 ; fused agg+norm+relu+split ----
    k_gemm_l01<<<dim3(nblk_gemm, 2), TB>>>(b0);
    k_aggnorm<<<nblk_wnode, TB>>>();

    // ---- layer 1 ----
    k_split_w<<<(DIMF * DIMF + TB - 1) / TB, TB>>>(Wl1, Wr1, DIMF * DIMF);
    k_gemm_l01<<<dim3(nblk_gemm, 2), TB>>>(b1);
    k_aggnorm<<<nblk_wnode, TB>>>();

    // ---- layer 2 (project-first, 40-dim gather + fused softmax) ----
    k_split_w2<<<(OUTD_F * DIMF + TB - 1) / TB, TB>>>(Wl2, Wr2);
    k_gemm2<<<nblk_gemm, TB>>>(b2);
    k_agg_softmax<<<nblk_wnode, TB>>>(out);
}